// round 1
// baseline (speedup 1.0000x reference)
#include <cuda_runtime.h>

// Shapes (fixed by the problem)
#define KTOT 784      // 28*28 input pixels = GEMM K
#define NHID 200      // hidden width = GEMM N
#define NCLS 10
#define BM   64       // rows per block
#define BK   28       // k-chunk (784 = 28*28)

// Effective first-layer weight: conv folded into w1.
__device__ float g_w1eff[KTOT * NHID];

// ---------------------------------------------------------------------------
// Kernel 1: W1eff[p][h] = sum over 3x3 taps (di,dj) with valid output pos:
//   conv_w[di][dj] * w1[(y-di)*26 + (x-dj)][h]
// ---------------------------------------------------------------------------
__global__ void build_w1eff_kernel(const float* __restrict__ conv_w,
                                   const float* __restrict__ w1) {
    int p = blockIdx.x;        // 0..783
    int h = threadIdx.x;       // 0..199
    int y = p / 28, xx = p % 28;
    float s = 0.f;
#pragma unroll
    for (int di = 0; di < 3; ++di) {
        int oy = y - di;
        if (oy < 0 || oy > 25) continue;
#pragma unroll
        for (int dj = 0; dj < 3; ++dj) {
            int ox = xx - dj;
            if (ox < 0 || ox > 25) continue;
            s += conv_w[di * 3 + dj] * w1[(oy * 26 + ox) * NHID + h];
        }
    }
    g_w1eff[p * NHID + h] = s;
}

// ---------------------------------------------------------------------------
// Kernel 2: fused  out = relu(x @ W1eff + b1) @ w2 + b2
// Block: 64 rows x full 200 cols. 256 threads; threads 0..199 own 8x8 tiles.
// Smem (union):
//   main loop : xs[28][64] (transposed x) | ws[28][200]        -> 29,568 B
//   epilogue  : hid[64][201] | w2s[200*10] | outp[64*10]       -> 62,016 B
// ---------------------------------------------------------------------------
#define SMEM_FLOATS (64 * 201 + NHID * NCLS + BM * NCLS)   // 15504
#define SMEM_BYTES  (SMEM_FLOATS * 4)                      // 62016

__global__ __launch_bounds__(256, 2)
void fused_mlp_kernel(const float* __restrict__ x,
                      const float* __restrict__ b1,
                      const float* __restrict__ w2,
                      const float* __restrict__ b2,
                      float* __restrict__ out) {
    extern __shared__ float sm[];
    float* xs = sm;                 // [BK][BM]  (k-major, transposed)
    float* ws = sm + BK * BM;       // [BK][NHID]

    const int tid = threadIdx.x;
    const int m0  = blockIdx.x * BM;
    const int tn  = tid % 25;       // 25 n-groups of 8 cols
    const int tm  = tid / 25;       // 8 m-groups of 8 rows (valid for tid<200)

    float acc[8][8];
#pragma unroll
    for (int i = 0; i < 8; ++i)
#pragma unroll
        for (int j = 0; j < 8; ++j) acc[i][j] = 0.f;

    for (int k0 = 0; k0 < KTOT; k0 += BK) {
        __syncthreads();
        // ---- load x tile (64 x 28) transposed into xs[k][m], float4 global loads
        for (int e = tid; e < (BM * BK) / 4; e += 256) {      // 448 float4
            int m = e / 7, kq = e % 7;
            float4 v = *(const float4*)&x[(m0 + m) * KTOT + k0 + kq * 4];
            xs[(kq * 4 + 0) * BM + m] = v.x;
            xs[(kq * 4 + 1) * BM + m] = v.y;
            xs[(kq * 4 + 2) * BM + m] = v.z;
            xs[(kq * 4 + 3) * BM + m] = v.w;
        }
        // ---- load W1eff tile (28 x 200), contiguous float4
        for (int e = tid; e < (BK * NHID) / 4; e += 256) {    // 1400 float4
            int k = e / 50, n4 = e % 50;
            *(float4*)&ws[k * NHID + n4 * 4] =
                *(const float4*)&g_w1eff[(k0 + k) * NHID + n4 * 4];
        }
        __syncthreads();

        if (tid < 200) {
#pragma unroll 4
            for (int k = 0; k < BK; ++k) {
                float4 xa = *(float4*)&xs[k * BM + tm * 8];
                float4 xb = *(float4*)&xs[k * BM + tm * 8 + 4];
                float4 wa = *(float4*)&ws[k * NHID + tn * 8];
                float4 wb = *(float4*)&ws[k * NHID + tn * 8 + 4];
                float xr[8] = {xa.x, xa.y, xa.z, xa.w, xb.x, xb.y, xb.z, xb.w};
                float wr[8] = {wa.x, wa.y, wa.z, wa.w, wb.x, wb.y, wb.z, wb.w};
#pragma unroll
                for (int i = 0; i < 8; ++i)
#pragma unroll
                    for (int j = 0; j < 8; ++j)
                        acc[i][j] += xr[i] * wr[j];
            }
        }
    }
    __syncthreads();   // all smem reads done; safe to repurpose

    // ---- epilogue: hidden -> smem (padded row 201 = conflict-free), then @ w2
    float* hid  = sm;                       // [64][201]
    float* w2s  = sm + 64 * 201;            // [200][10]
    float* outp = w2s + NHID * NCLS;        // [64][10]

    if (tid < 200) {
#pragma unroll
        for (int i = 0; i < 8; ++i) {
            int m = tm * 8 + i;
#pragma unroll
            for (int j = 0; j < 8; ++j) {
                int n = tn * 8 + j;
                hid[m * 201 + n] = fmaxf(acc[i][j] + b1[n], 0.f);
            }
        }
    }
    for (int e = tid; e < NHID * NCLS; e += 256) w2s[e] = w2[e];
    for (int e = tid; e < BM * NCLS; e += 256) outp[e] = 0.f;
    __syncthreads();

    {
        int m  = tid & 63;
        int q  = tid >> 6;                  // 4 k-slices of 50
        float p[NCLS];
#pragma unroll
        for (int c = 0; c < NCLS; ++c) p[c] = 0.f;
        int h0 = q * 50;
        for (int h = h0; h < h0 + 50; ++h) {
            float v = hid[m * 201 + h];
#pragma unroll
            for (int c = 0; c < NCLS; ++c) p[c] += v * w2s[h * NCLS + c];
        }
#pragma unroll
        for (int c = 0; c < NCLS; ++c) atomicAdd(&outp[m * NCLS + c], p[c]);
    }
    __syncthreads();

    for (int e = tid; e < BM * NCLS; e += 256)
        out[m0 * NCLS + e] = outp[e] + b2[e % NCLS];
}

// ---------------------------------------------------------------------------
extern "C" void kernel_launch(void* const* d_in, const int* in_sizes, int n_in,
                              void* d_out, int out_size) {
    const float* x      = (const float*)d_in[0];   // [65536, 784]
    const float* conv_w = (const float*)d_in[1];   // [3, 3]
    const float* w1     = (const float*)d_in[2];   // [676, 200]
    const float* b1     = (const float*)d_in[3];   // [200]
    const float* w2     = (const float*)d_in[4];   // [200, 10]
    const float* b2     = (const float*)d_in[5];   // [10]
    float* out          = (float*)d_out;           // [65536, 10]

    // >48KB dynamic smem opt-in (idempotent; legal during graph capture)
    cudaFuncSetAttribute(fused_mlp_kernel,
                         cudaFuncAttributeMaxDynamicSharedMemorySize, SMEM_BYTES);

    build_w1eff_kernel<<<KTOT, NHID>>>(conv_w, w1);
    fused_mlp_kernel<<<65536 / BM, 256, SMEM_BYTES>>>(x, b1, w2, b2, out);
}

// round 3
// speedup vs baseline: 2.7903x; 2.7903x over previous
#include <cuda_runtime.h>
#include <cuda_bf16.h>
#include <cstdint>

// ---------------- problem constants ----------------
#define KTOT 784            // 28*28 GEMM K
#define NHID 200            // hidden width
#define NPAD 208            // N padded to 26*8
#define NCLS 10
#define BM   128            // rows per CTA
#define BK   64             // K per chunk
#define NCHUNK 13           // 13*64 = 832 (K zero-padded)
#define ROWB 144            // bytes per bf16 row (64*2 + 16 pad) -> LDSM conflict-free
#define ACH  (BM * ROWB)    // 18432 per term
#define BCH  (NPAD * ROWB)  // 29952 per term

// ---------------- smem layout (bytes) ----------------
#define SM_MB0   0
#define SM_MB1   8
#define SM_W2    64                         // 2000 floats
#define SM_B1    8064                       // 200 floats
#define SM_B2    8864                       // 10 floats
#define SM_ABASE 9216
#define SM_A(s, t) (SM_ABASE + ((s) * 2 + (t)) * ACH)          // 4 x 18432
#define SM_BBASE (SM_ABASE + 4 * ACH)                          // 82944
#define SM_B(s, t) (SM_BBASE + ((s) * 2 + (t)) * BCH)          // 4 x 29952
#define SMEM_TOTAL (SM_BBASE + 4 * BCH)                        // 202752
// epilogue reuse
#define SM_HID   9216                       // 128 x 210 floats
#define HSTRIDE  210
#define SM_OUTP  (SM_HID + BM * HSTRIDE * 4)

// Per-chunk images of W1eff^T (n-major rows, 144B stride) in bf16 hi/lo.
__device__ __align__(16) unsigned char g_wB_hi[NCHUNK * BCH];
__device__ __align__(16) unsigned char g_wB_lo[NCHUNK * BCH];

// ---------------- PTX helpers ----------------
__device__ __forceinline__ uint32_t smem_u32(const void* p) {
    uint32_t a;
    asm("{ .reg .u64 t; cvta.to.shared.u64 t, %1; cvt.u32.u64 %0, t; }" : "=r"(a) : "l"(p));
    return a;
}

#define MBARRIER_INIT(a, n) \
    asm volatile("mbarrier.init.shared.b64 [%0], %1;" :: "r"(a), "r"((uint32_t)(n)) : "memory")
#define MBARRIER_EXPECT_TX(a, b) \
    asm volatile("mbarrier.arrive.expect_tx.shared.b64 _, [%0], %1;" :: "r"(a), "r"((uint32_t)(b)) : "memory")

#define MBARRIER_WAIT_PARITY(mbar, par) do {                                   \
    uint32_t _m = (mbar), _p = (par), _d;                                      \
    asm volatile("{\n\t.reg .pred p;\n\t"                                      \
        "mbarrier.try_wait.parity.acquire.cta.shared::cta.b64 p, [%1], %2;\n\t"\
        "selp.b32 %0, 1, 0, p;\n\t}"                                           \
        : "=r"(_d) : "r"(_m), "r"(_p) : "memory");                             \
    if (!_d) {                                                                 \
        asm volatile("{\n\t.reg .pred P1;\n\t"                                 \
            "W%=:\n\t"                                                         \
            "mbarrier.try_wait.parity.acquire.cta.shared::cta.b64 P1, [%0], %1, 0x989680;\n\t" \
            "@P1 bra.uni D%=;\n\t"                                             \
            "bra.uni W%=;\n\t"                                                 \
            "D%=:\n\t}" :: "r"(_m), "r"(_p) : "memory");                       \
    }                                                                          \
} while (0)

__device__ __forceinline__ void bulk_g2s(uint32_t dst, const void* src, uint32_t bytes, uint32_t mbar) {
    asm volatile("cp.async.bulk.shared::cta.global.mbarrier::complete_tx::bytes [%0], [%1], %2, [%3];"
        :: "r"(dst), "l"(src), "r"(bytes), "r"(mbar) : "memory");
}

__device__ __forceinline__ void ldsm4(uint32_t* d, uint32_t addr) {
    asm volatile("ldmatrix.sync.aligned.m8n8.x4.shared.b16 {%0,%1,%2,%3}, [%4];"
        : "=r"(d[0]), "=r"(d[1]), "=r"(d[2]), "=r"(d[3]) : "r"(addr));
}
__device__ __forceinline__ void ldsm2(uint32_t* d, uint32_t addr) {
    asm volatile("ldmatrix.sync.aligned.m8n8.x2.shared.b16 {%0,%1}, [%2];"
        : "=r"(d[0]), "=r"(d[1]) : "r"(addr));
}
__device__ __forceinline__ void mma16816(float* c, const uint32_t* a, const uint32_t* b) {
    asm volatile("mma.sync.aligned.m16n8k16.row.col.f32.bf16.bf16.f32 "
        "{%0,%1,%2,%3}, {%4,%5,%6,%7}, {%8,%9}, {%0,%1,%2,%3};"
        : "+f"(c[0]), "+f"(c[1]), "+f"(c[2]), "+f"(c[3])
        : "r"(a[0]), "r"(a[1]), "r"(a[2]), "r"(a[3]), "r"(b[0]), "r"(b[1]));
}

// ---------------------------------------------------------------------------
// Prep: W1eff[k][n] = conv folded into w1; store transposed [n][k] rows,
// bf16 hi (truncation) + bf16 lo (rn of residual), 144B row stride.
// ---------------------------------------------------------------------------
__global__ void prep_kernel(const float* __restrict__ conv_w, const float* __restrict__ w1) {
    int p = blockIdx.x;    // k: 0..831
    int h = threadIdx.x;   // n: 0..207
    float s = 0.f;
    if (p < KTOT && h < NHID) {
        int y = p / 28, xx = p % 28;
#pragma unroll
        for (int di = 0; di < 3; ++di) {
            int oy = y - di;
            if (oy < 0 || oy > 25) continue;
#pragma unroll
            for (int dj = 0; dj < 3; ++dj) {
                int ox = xx - dj;
                if (ox < 0 || ox > 25) continue;
                s += conv_w[di * 3 + dj] * w1[(oy * 26 + ox) * NHID + h];
            }
        }
    }
    uint32_t sb  = __float_as_uint(s);
    uint32_t hib = sb & 0xFFFF0000u;
    float r = s - __uint_as_float(hib);
    __nv_bfloat16 lo16 = __float2bfloat16(r);
    unsigned short lo_us = *reinterpret_cast<unsigned short*>(&lo16);

    int chunk = p >> 6, kl = p & 63;
    size_t off = (size_t)chunk * BCH + (size_t)h * ROWB + (size_t)kl * 2;
    *(unsigned short*)(g_wB_hi + off) = (unsigned short)(hib >> 16);
    *(unsigned short*)(g_wB_lo + off) = lo_us;
}

// Split 8 fp32 into bf16-hi (trunc) + bf16-lo (rn residual), packed pairs.
__device__ __forceinline__ void split8(float4 v0, float4 v1, uint4& hi, uint4& lo) {
    uint32_t a[8] = {__float_as_uint(v0.x), __float_as_uint(v0.y), __float_as_uint(v0.z), __float_as_uint(v0.w),
                     __float_as_uint(v1.x), __float_as_uint(v1.y), __float_as_uint(v1.z), __float_as_uint(v1.w)};
    uint32_t rb[8];
#pragma unroll
    for (int i = 0; i < 8; ++i) {
        float t = __uint_as_float(a[i] & 0xFFFF0000u);
        float res = __uint_as_float(a[i]) - t;
        __nv_bfloat16 lb = __float2bfloat16(res);
        rb[i] = (uint32_t)(*reinterpret_cast<unsigned short*>(&lb)) << 16;
    }
    hi.x = __byte_perm(a[0], a[1], 0x7632); hi.y = __byte_perm(a[2], a[3], 0x7632);
    hi.z = __byte_perm(a[4], a[5], 0x7632); hi.w = __byte_perm(a[6], a[7], 0x7632);
    lo.x = __byte_perm(rb[0], rb[1], 0x7632); lo.y = __byte_perm(rb[2], rb[3], 0x7632);
    lo.z = __byte_perm(rb[4], rb[5], 0x7632); lo.w = __byte_perm(rb[6], rb[7], 0x7632);
}

// A tile convert: x[128 x 64] fp32 -> bf16 hi/lo rows (144B stride)
__device__ __forceinline__ void convertA(const float* __restrict__ x, int m0, int chunk,
                                         unsigned char* smem, int stage, int tid) {
    const int k0 = chunk * BK;
    unsigned char* Ahi = smem + SM_A(stage, 0);
    unsigned char* Alo = smem + SM_A(stage, 1);
#pragma unroll
    for (int it = 0; it < 4; ++it) {
        int t = tid + it * 256;          // 0..1023
        int m = t >> 3, g = t & 7;
        int kg = k0 + g * 8;
        uint4 hi = {0, 0, 0, 0}, lo = {0, 0, 0, 0};
        if (kg < KTOT) {
            const float4* src = (const float4*)(x + (size_t)(m0 + m) * KTOT + kg);
            split8(src[0], src[1], hi, lo);
        }
        uint32_t so = (uint32_t)m * ROWB + (uint32_t)g * 16;
        *(uint4*)(Ahi + so) = hi;
        *(uint4*)(Alo + so) = lo;
    }
}

// ---------------------------------------------------------------------------
// Fused: out = relu(X @ W1eff + b1) @ w2 + b2  (split-bf16 mma.sync)
// 8 warps = 4m x 2n; warp tile 32(m) x 104(n); acc = 2x13 m16n8 tiles.
// ---------------------------------------------------------------------------
__global__ __launch_bounds__(256, 1)
void fused_mma_kernel(const float* __restrict__ x,
                      const float* __restrict__ b1,
                      const float* __restrict__ w2,
                      const float* __restrict__ b2,
                      float* __restrict__ out) {
    extern __shared__ __align__(1024) unsigned char smem[];
    const uint32_t sb = smem_u32(smem);
    const int tid  = threadIdx.x;
    const int wid  = tid >> 5;
    const int lane = tid & 31;
    const int m0   = blockIdx.x * BM;

    const int wm = (wid >> 1) * 32;     // warp m base (rows)
    const int wn = (wid & 1) * 104;     // warp n base (cols)

    float* w2s = (float*)(smem + SM_W2);
    float* b1s = (float*)(smem + SM_B1);
    float* b2s = (float*)(smem + SM_B2);

    if (tid == 0) {
        MBARRIER_INIT(sb + SM_MB0, 1);
        MBARRIER_INIT(sb + SM_MB1, 1);
    }
    for (int e = tid; e < NHID * NCLS; e += 256) w2s[e] = w2[e];
    for (int e = tid; e < NHID; e += 256)        b1s[e] = b1[e];
    if (tid < NCLS)                              b2s[tid] = b2[tid];
    __syncthreads();

    // per-lane ldmatrix offsets (row within 16, 16B k-halves)
    const int lg = lane >> 3, lr = lane & 7;
    const uint32_t a_off = (uint32_t)(((lg & 1) * 8 + lr) * ROWB + (lg >> 1) * 16);
    const uint32_t b_off = (uint32_t)(((lg >> 1) * 8 + lr) * ROWB + (lg & 1) * 16);

    float acc[104];
#pragma unroll
    for (int i = 0; i < 104; ++i) acc[i] = 0.f;

    // prologue: chunk 0 in flight
    if (tid == 0) {
        MBARRIER_EXPECT_TX(sb + SM_MB0, 2 * BCH);
        bulk_g2s(sb + SM_B(0, 0), g_wB_hi, BCH, sb + SM_MB0);
        bulk_g2s(sb + SM_B(0, 1), g_wB_lo, BCH, sb + SM_MB0);
    }
    convertA(x, m0, 0, smem, 0, tid);
    __syncthreads();

    for (int i = 0; i < NCHUNK; ++i) {
        const int s = i & 1;
        // prefetch next chunk into the other stage (freed by sync at iter end)
        if (i + 1 < NCHUNK) {
            const uint32_t mb = (s ? sb + SM_MB0 : sb + SM_MB1);
            if (tid == 0) {
                MBARRIER_EXPECT_TX(mb, 2 * BCH);
                bulk_g2s(sb + SM_B(1 - s, 0), g_wB_hi + (size_t)(i + 1) * BCH, BCH, mb);
                bulk_g2s(sb + SM_B(1 - s, 1), g_wB_lo + (size_t)(i + 1) * BCH, BCH, mb);
            }
            convertA(x, m0, i + 1, smem, 1 - s, tid);
        }
        // wait for this chunk's B tiles
        MBARRIER_WAIT_PARITY((s ? sb + SM_MB1 : sb + SM_MB0), (i >> 1) & 1);

        const uint32_t aHiB = sb + SM_A(s, 0) + (uint32_t)wm * ROWB;
        const uint32_t aLoB = sb + SM_A(s, 1) + (uint32_t)wm * ROWB;
        const uint32_t bHiB = sb + SM_B(s, 0) + (uint32_t)wn * ROWB;
        const uint32_t bLoB = sb + SM_B(s, 1) + (uint32_t)wn * ROWB;

#pragma unroll
        for (int ks = 0; ks < 4; ++ks) {
            const uint32_t kb = (uint32_t)ks * 32;
            uint32_t bf[26], af0[4], af1[4];

            // ---- term 1: A_hi x B_hi
#pragma unroll
            for (int tp = 0; tp < 6; ++tp) ldsm4(&bf[tp * 4], bHiB + tp * (16 * ROWB) + kb + b_off);
            ldsm2(&bf[24], bHiB + 6 * (16 * ROWB) + kb + b_off);
            ldsm4(af0, aHiB + kb + a_off);
            ldsm4(af1, aHiB + 16 * ROWB + kb + a_off);
#pragma unroll
            for (int tn = 0; tn < 13; ++tn) {
                mma16816(&acc[tn * 4], af0, &bf[tn * 2]);
                mma16816(&acc[52 + tn * 4], af1, &bf[tn * 2]);
            }
            // ---- term 2: A_lo x B_hi
            ldsm4(af0, aLoB + kb + a_off);
            ldsm4(af1, aLoB + 16 * ROWB + kb + a_off);
#pragma unroll
            for (int tn = 0; tn < 13; ++tn) {
                mma16816(&acc[tn * 4], af0, &bf[tn * 2]);
                mma16816(&acc[52 + tn * 4], af1, &bf[tn * 2]);
            }
            // ---- term 3: A_hi x B_lo
#pragma unroll
            for (int tp = 0; tp < 6; ++tp) ldsm4(&bf[tp * 4], bLoB + tp * (16 * ROWB) + kb + b_off);
            ldsm2(&bf[24], bLoB + 6 * (16 * ROWB) + kb + b_off);
            ldsm4(af0, aHiB + kb + a_off);
            ldsm4(af1, aHiB + 16 * ROWB + kb + a_off);
#pragma unroll
            for (int tn = 0; tn < 13; ++tn) {
                mma16816(&acc[tn * 4], af0, &bf[tn * 2]);
                mma16816(&acc[52 + tn * 4], af1, &bf[tn * 2]);
            }
        }
        __syncthreads();
    }

    // ---------------- epilogue: relu(+b1) -> smem, then @ w2 + b2 ----------------
    float* hid  = (float*)(smem + SM_HID);    // [128][210]
    float* outp = (float*)(smem + SM_OUTP);   // [128][10]

#pragma unroll
    for (int tm = 0; tm < 2; ++tm) {
#pragma unroll
        for (int tn = 0; tn < 13; ++tn) {
            int c = wn + tn * 8 + (lane & 3) * 2;
            if (c < NHID) {
                int r0 = wm + tm * 16 + (lane >> 2);
                float b1a = b1s[c], b1b = b1s[c + 1];
                const float* a = &acc[tm * 52 + tn * 4];
                hid[r0 * HSTRIDE + c]           = fmaxf(a[0] + b1a, 0.f);
                hid[r0 * HSTRIDE + c + 1]       = fmaxf(a[1] + b1b, 0.f);
                hid[(r0 + 8) * HSTRIDE + c]     = fmaxf(a[2] + b1a, 0.f);
                hid[(r0 + 8) * HSTRIDE + c + 1] = fmaxf(a[3] + b1b, 0.f);
            }
        }
    }
    for (int e = tid; e < BM * NCLS; e += 256) outp[e] = 0.f;
    __syncthreads();

    {
        int m  = tid >> 1;
        int h0 = (tid & 1) * 100;
        float p[NCLS];
#pragma unroll
        for (int c = 0; c < NCLS; ++c) p[c] = 0.f;
        for (int h = h0; h < h0 + 100; ++h) {
            float v = hid[m * HSTRIDE + h];
#pragma unroll
            for (int c = 0; c < NCLS; ++c) p[c] += v * w2s[h * NCLS + c];
        }
#pragma unroll
        for (int c = 0; c < NCLS; ++c) atomicAdd(&outp[m * NCLS + c], p[c]);
    }
    __syncthreads();

    for (int e = tid; e < BM * NCLS; e += 256)
        out[(size_t)m0 * NCLS + e] = outp[e] + b2s[e % NCLS];
}

// ---------------------------------------------------------------------------
extern "C" void kernel_launch(void* const* d_in, const int* in_sizes, int n_in,
                              void* d_out, int out_size) {
    const float* x      = (const float*)d_in[0];   // [65536, 784]
    const float* conv_w = (const float*)d_in[1];   // [3, 3]
    const float* w1     = (const float*)d_in[2];   // [676, 200]
    const float* b1     = (const float*)d_in[3];   // [200]
    const float* w2     = (const float*)d_in[4];   // [200, 10]
    const float* b2     = (const float*)d_in[5];   // [10]
    float* out          = (float*)d_out;           // [65536, 10]

    cudaFuncSetAttribute(fused_mma_kernel,
                         cudaFuncAttributeMaxDynamicSharedMemorySize, SMEM_TOTAL);

    prep_kernel<<<NCHUNK * BK, NPAD>>>(conv_w, w1);
    fused_mma_kernel<<<65536 / BM, 256, SMEM_TOTAL>>>(x, b1, w2, b2, out);
}

// round 4
// speedup vs baseline: 3.2069x; 1.1493x over previous
#include <cuda_runtime.h>
#include <cuda_bf16.h>
#include <cstdint>

// ---------------- problem constants ----------------
#define KTOT 784            // 28*28 GEMM K
#define NHID 200            // hidden width
#define NPAD 208            // N padded to 26*8
#define NCLS 10
#define BM   128            // rows per CTA
#define BK   64             // K per chunk
#define NCHUNK 13           // 13*64 = 832 (K zero-padded)
#define ROWB 144            // bytes per bf16 row (64*2 + 16 pad) -> LDSM conflict-free
#define ACH  (BM * ROWB)    // 18432 per term
#define BCH  (NPAD * ROWB)  // 29952 per term
#define NTHREADS 512

// ---------------- smem layout (bytes) ----------------
#define SM_MB0   0
#define SM_MB1   8
#define SM_W2    64                         // 2000 floats
#define SM_B1    8064                       // 200 floats
#define SM_B2    8864                       // 10 floats
#define SM_ABASE 9216
#define SM_A(s, t) (SM_ABASE + ((s) * 2 + (t)) * ACH)          // 4 x 18432
#define SM_BBASE (SM_ABASE + 4 * ACH)                          // 82944
#define SM_B(s, t) (SM_BBASE + ((s) * 2 + (t)) * BCH)          // 4 x 29952
#define SMEM_TOTAL (SM_BBASE + 4 * BCH)                        // 202752
// epilogue reuse
#define SM_HID   9216                       // 128 x 210 floats
#define HSTRIDE  210
#define SM_OUTP  (SM_HID + BM * HSTRIDE * 4)

// Per-chunk images of W1eff^T (n-major rows, 144B stride) in bf16 hi/lo.
__device__ __align__(16) unsigned char g_wB_hi[NCHUNK * BCH];
__device__ __align__(16) unsigned char g_wB_lo[NCHUNK * BCH];

// ---------------- PTX helpers ----------------
__device__ __forceinline__ uint32_t smem_u32(const void* p) {
    uint32_t a;
    asm("{ .reg .u64 t; cvta.to.shared.u64 t, %1; cvt.u32.u64 %0, t; }" : "=r"(a) : "l"(p));
    return a;
}

#define MBARRIER_INIT(a, n) \
    asm volatile("mbarrier.init.shared.b64 [%0], %1;" :: "r"(a), "r"((uint32_t)(n)) : "memory")
#define MBARRIER_EXPECT_TX(a, b) \
    asm volatile("mbarrier.arrive.expect_tx.shared.b64 _, [%0], %1;" :: "r"(a), "r"((uint32_t)(b)) : "memory")

#define MBARRIER_WAIT_PARITY(mbar, par) do {                                   \
    uint32_t _m = (mbar), _p = (par), _d;                                      \
    asm volatile("{\n\t.reg .pred p;\n\t"                                      \
        "mbarrier.try_wait.parity.acquire.cta.shared::cta.b64 p, [%1], %2;\n\t"\
        "selp.b32 %0, 1, 0, p;\n\t}"                                           \
        : "=r"(_d) : "r"(_m), "r"(_p) : "memory");                             \
    if (!_d) {                                                                 \
        asm volatile("{\n\t.reg .pred P1;\n\t"                                 \
            "W%=:\n\t"                                                         \
            "mbarrier.try_wait.parity.acquire.cta.shared::cta.b64 P1, [%0], %1, 0x989680;\n\t" \
            "@P1 bra.uni D%=;\n\t"                                             \
            "bra.uni W%=;\n\t"                                                 \
            "D%=:\n\t}" :: "r"(_m), "r"(_p) : "memory");                       \
    }                                                                          \
} while (0)

__device__ __forceinline__ void bulk_g2s(uint32_t dst, const void* src, uint32_t bytes, uint32_t mbar) {
    asm volatile("cp.async.bulk.shared::cta.global.mbarrier::complete_tx::bytes [%0], [%1], %2, [%3];"
        :: "r"(dst), "l"(src), "r"(bytes), "r"(mbar) : "memory");
}

__device__ __forceinline__ void ldsm4(uint32_t* d, uint32_t addr) {
    asm volatile("ldmatrix.sync.aligned.m8n8.x4.shared.b16 {%0,%1,%2,%3}, [%4];"
        : "=r"(d[0]), "=r"(d[1]), "=r"(d[2]), "=r"(d[3]) : "r"(addr));
}
__device__ __forceinline__ void ldsm2(uint32_t* d, uint32_t addr) {
    asm volatile("ldmatrix.sync.aligned.m8n8.x2.shared.b16 {%0,%1}, [%2];"
        : "=r"(d[0]), "=r"(d[1]) : "r"(addr));
}
__device__ __forceinline__ void mma16816(float* c, const uint32_t* a, const uint32_t* b) {
    asm volatile("mma.sync.aligned.m16n8k16.row.col.f32.bf16.bf16.f32 "
        "{%0,%1,%2,%3}, {%4,%5,%6,%7}, {%8,%9}, {%0,%1,%2,%3};"
        : "+f"(c[0]), "+f"(c[1]), "+f"(c[2]), "+f"(c[3])
        : "r"(a[0]), "r"(a[1]), "r"(a[2]), "r"(a[3]), "r"(b[0]), "r"(b[1]));
}

// ---------------------------------------------------------------------------
// Prep: W1eff[k][n] = conv folded into w1; store transposed [n][k] rows,
// bf16 hi (truncation) + bf16 lo (rn of residual), 144B row stride.
// ---------------------------------------------------------------------------
__global__ void prep_kernel(const float* __restrict__ conv_w, const float* __restrict__ w1) {
    int p = blockIdx.x;    // k: 0..831
    int h = threadIdx.x;   // n: 0..207
    float s = 0.f;
    if (p < KTOT && h < NHID) {
        int y = p / 28, xx = p % 28;
#pragma unroll
        for (int di = 0; di < 3; ++di) {
            int oy = y - di;
            if (oy < 0 || oy > 25) continue;
#pragma unroll
            for (int dj = 0; dj < 3; ++dj) {
                int ox = xx - dj;
                if (ox < 0 || ox > 25) continue;
                s += conv_w[di * 3 + dj] * w1[(oy * 26 + ox) * NHID + h];
            }
        }
    }
    uint32_t sb  = __float_as_uint(s);
    uint32_t hib = sb & 0xFFFF0000u;
    float r = s - __uint_as_float(hib);
    __nv_bfloat16 lo16 = __float2bfloat16(r);
    unsigned short lo_us = *reinterpret_cast<unsigned short*>(&lo16);

    int chunk = p >> 6, kl = p & 63;
    size_t off = (size_t)chunk * BCH + (size_t)h * ROWB + (size_t)kl * 2;
    *(unsigned short*)(g_wB_hi + off) = (unsigned short)(hib >> 16);
    *(unsigned short*)(g_wB_lo + off) = lo_us;
}

// Split 8 fp32 into bf16-hi (trunc) + bf16-lo (rn residual), packed pairs.
__device__ __forceinline__ void split8(float4 v0, float4 v1, uint4& hi, uint4& lo) {
    uint32_t a[8] = {__float_as_uint(v0.x), __float_as_uint(v0.y), __float_as_uint(v0.z), __float_as_uint(v0.w),
                     __float_as_uint(v1.x), __float_as_uint(v1.y), __float_as_uint(v1.z), __float_as_uint(v1.w)};
    uint32_t rb[8];
#pragma unroll
    for (int i = 0; i < 8; ++i) {
        float t = __uint_as_float(a[i] & 0xFFFF0000u);
        float res = __uint_as_float(a[i]) - t;
        __nv_bfloat16 lb = __float2bfloat16(res);
        rb[i] = (uint32_t)(*reinterpret_cast<unsigned short*>(&lb)) << 16;
    }
    hi.x = __byte_perm(a[0], a[1], 0x7632); hi.y = __byte_perm(a[2], a[3], 0x7632);
    hi.z = __byte_perm(a[4], a[5], 0x7632); hi.w = __byte_perm(a[6], a[7], 0x7632);
    lo.x = __byte_perm(rb[0], rb[1], 0x7632); lo.y = __byte_perm(rb[2], rb[3], 0x7632);
    lo.z = __byte_perm(rb[4], rb[5], 0x7632); lo.w = __byte_perm(rb[6], rb[7], 0x7632);
}

// A tile convert: x[128 x 64] fp32 -> bf16 hi/lo rows (144B stride)
__device__ __forceinline__ void convertA(const float* __restrict__ x, int m0, int chunk,
                                         unsigned char* smem, int stage, int tid) {
    const int k0 = chunk * BK;
    unsigned char* Ahi = smem + SM_A(stage, 0);
    unsigned char* Alo = smem + SM_A(stage, 1);
#pragma unroll
    for (int it = 0; it < 2; ++it) {
        int t = tid + it * NTHREADS;     // 0..1023
        int m = t >> 3, g = t & 7;
        int kg = k0 + g * 8;
        uint4 hi = {0, 0, 0, 0}, lo = {0, 0, 0, 0};
        if (kg < KTOT) {
            const float4* src = (const float4*)(x + (size_t)(m0 + m) * KTOT + kg);
            split8(src[0], src[1], hi, lo);
        }
        uint32_t so = (uint32_t)m * ROWB + (uint32_t)g * 16;
        *(uint4*)(Ahi + so) = hi;
        *(uint4*)(Alo + so) = lo;
    }
}

// ---------------------------------------------------------------------------
// Fused: out = relu(X @ W1eff + b1) @ w2 + b2  (split-bf16 mma.sync)
// 16 warps = 8m x 2n; warp tile 16(m) x 104(n); acc = 13 m16n8 tiles (52 regs).
// ---------------------------------------------------------------------------
__global__ __launch_bounds__(NTHREADS, 1)
void fused_mma_kernel(const float* __restrict__ x,
                      const float* __restrict__ b1,
                      const float* __restrict__ w2,
                      const float* __restrict__ b2,
                      float* __restrict__ out) {
    extern __shared__ __align__(1024) unsigned char smem[];
    const uint32_t sb = smem_u32(smem);
    const int tid  = threadIdx.x;
    const int wid  = tid >> 5;
    const int lane = tid & 31;
    const int m0   = blockIdx.x * BM;

    const int wm = (wid >> 1) * 16;     // warp m base (rows)
    const int wn = (wid & 1) * 104;     // warp n base (cols)

    float* w2s = (float*)(smem + SM_W2);
    float* b1s = (float*)(smem + SM_B1);
    float* b2s = (float*)(smem + SM_B2);

    if (tid == 0) {
        MBARRIER_INIT(sb + SM_MB0, 1);
        MBARRIER_INIT(sb + SM_MB1, 1);
    }
    for (int e = tid; e < NHID * NCLS; e += NTHREADS) w2s[e] = w2[e];
    for (int e = tid; e < NHID; e += NTHREADS)        b1s[e] = b1[e];
    if (tid < NCLS)                                   b2s[tid] = b2[tid];
    __syncthreads();

    // per-lane ldmatrix offsets (row within 16, 16B k-halves)
    const int lg = lane >> 3, lr = lane & 7;
    const uint32_t a_off = (uint32_t)(((lg & 1) * 8 + lr) * ROWB + (lg >> 1) * 16);
    const uint32_t b_off = (uint32_t)(((lg >> 1) * 8 + lr) * ROWB + (lg & 1) * 16);

    float acc[52];
#pragma unroll
    for (int i = 0; i < 52; ++i) acc[i] = 0.f;

    // prologue: chunk 0 in flight
    if (tid == 0) {
        MBARRIER_EXPECT_TX(sb + SM_MB0, 2 * BCH);
        bulk_g2s(sb + SM_B(0, 0), g_wB_hi, BCH, sb + SM_MB0);
        bulk_g2s(sb + SM_B(0, 1), g_wB_lo, BCH, sb + SM_MB0);
    }
    convertA(x, m0, 0, smem, 0, tid);
    __syncthreads();

    for (int i = 0; i < NCHUNK; ++i) {
        const int s = i & 1;
        // prefetch next chunk into the other stage (freed by sync at iter end)
        if (i + 1 < NCHUNK) {
            const uint32_t mb = (s ? sb + SM_MB0 : sb + SM_MB1);
            if (tid == 0) {
                MBARRIER_EXPECT_TX(mb, 2 * BCH);
                bulk_g2s(sb + SM_B(1 - s, 0), g_wB_hi + (size_t)(i + 1) * BCH, BCH, mb);
                bulk_g2s(sb + SM_B(1 - s, 1), g_wB_lo + (size_t)(i + 1) * BCH, BCH, mb);
            }
            convertA(x, m0, i + 1, smem, 1 - s, tid);
        }
        // wait for this chunk's B tiles
        MBARRIER_WAIT_PARITY((s ? sb + SM_MB1 : sb + SM_MB0), (i >> 1) & 1);

        const uint32_t aHiB = sb + SM_A(s, 0) + (uint32_t)wm * ROWB;
        const uint32_t aLoB = sb + SM_A(s, 1) + (uint32_t)wm * ROWB;
        const uint32_t bHiB = sb + SM_B(s, 0) + (uint32_t)wn * ROWB;
        const uint32_t bLoB = sb + SM_B(s, 1) + (uint32_t)wn * ROWB;

#pragma unroll
        for (int ks = 0; ks < 4; ++ks) {
            const uint32_t kb = (uint32_t)ks * 32;
            uint32_t bf[26], afh[4], afl[4];

            // A fragments for this k-step (hi + lo)
            ldsm4(afh, aHiB + kb + a_off);
            ldsm4(afl, aLoB + kb + a_off);

            // ---- B_hi: terms A_hi x B_hi and A_lo x B_hi
#pragma unroll
            for (int tp = 0; tp < 6; ++tp) ldsm4(&bf[tp * 4], bHiB + tp * (16 * ROWB) + kb + b_off);
            ldsm2(&bf[24], bHiB + 6 * (16 * ROWB) + kb + b_off);
#pragma unroll
            for (int tn = 0; tn < 13; ++tn) mma16816(&acc[tn * 4], afh, &bf[tn * 2]);
#pragma unroll
            for (int tn = 0; tn < 13; ++tn) mma16816(&acc[tn * 4], afl, &bf[tn * 2]);

            // ---- B_lo: term A_hi x B_lo
#pragma unroll
            for (int tp = 0; tp < 6; ++tp) ldsm4(&bf[tp * 4], bLoB + tp * (16 * ROWB) + kb + b_off);
            ldsm2(&bf[24], bLoB + 6 * (16 * ROWB) + kb + b_off);
#pragma unroll
            for (int tn = 0; tn < 13; ++tn) mma16816(&acc[tn * 4], afh, &bf[tn * 2]);
        }
        __syncthreads();
    }

    // ---------------- epilogue: relu(+b1) -> smem, then @ w2 + b2 ----------------
    float* hid  = (float*)(smem + SM_HID);    // [128][210]
    float* outp = (float*)(smem + SM_OUTP);   // [128][10]

#pragma unroll
    for (int tn = 0; tn < 13; ++tn) {
        int c = wn + tn * 8 + (lane & 3) * 2;
        if (c < NHID) {
            int r0 = wm + (lane >> 2);
            float b1a = b1s[c], b1b = b1s[c + 1];
            const float* a = &acc[tn * 4];
            hid[r0 * HSTRIDE + c]           = fmaxf(a[0] + b1a, 0.f);
            hid[r0 * HSTRIDE + c + 1]       = fmaxf(a[1] + b1b, 0.f);
            hid[(r0 + 8) * HSTRIDE + c]     = fmaxf(a[2] + b1a, 0.f);
            hid[(r0 + 8) * HSTRIDE + c + 1] = fmaxf(a[3] + b1b, 0.f);
        }
    }
    for (int e = tid; e < BM * NCLS; e += NTHREADS) outp[e] = 0.f;
    __syncthreads();

    {
        int m  = tid >> 2;                  // 0..127
        int h0 = (tid & 3) * 50;            // 4 k-slices of 50
        float p[NCLS];
#pragma unroll
        for (int c = 0; c < NCLS; ++c) p[c] = 0.f;
        for (int h = h0; h < h0 + 50; ++h) {
            float v = hid[m * HSTRIDE + h];
#pragma unroll
            for (int c = 0; c < NCLS; ++c) p[c] += v * w2s[h * NCLS + c];
        }
#pragma unroll
        for (int c = 0; c < NCLS; ++c) atomicAdd(&outp[m * NCLS + c], p[c]);
    }
    __syncthreads();

    for (int e = tid; e < BM * NCLS; e += NTHREADS)
        out[(size_t)m0 * NCLS + e] = outp[e] + b2s[e % NCLS];
}

// ---------------------------------------------------------------------------
extern "C" void kernel_launch(void* const* d_in, const int* in_sizes, int n_in,
                              void* d_out, int out_size) {
    const float* x      = (const float*)d_in[0];   // [65536, 784]
    const float* conv_w = (const float*)d_in[1];   // [3, 3]
    const float* w1     = (const float*)d_in[2];   // [676, 200]
    const float* b1     = (const float*)d_in[3];   // [200]
    const float* w2     = (const float*)d_in[4];   // [200, 10]
    const float* b2     = (const float*)d_in[5];   // [10]
    float* out          = (float*)d_out;           // [65536, 10]

    cudaFuncSetAttribute(fused_mma_kernel,
                         cudaFuncAttributeMaxDynamicSharedMemorySize, SMEM_TOTAL);

    prep_kernel<<<NCHUNK * BK, NPAD>>>(conv_w, w1);
    fused_mma_kernel<<<65536 / BM, NTHREADS, SMEM_TOTAL>>>(x, b1, w2, b2, out);
}